// round 14
// baseline (speedup 1.0000x reference)
#include <cuda_runtime.h>
#include <cuda_fp16.h>
#include <stdint.h>
#include <math.h>

#define TSEQ 512
#define NBH 32
#define HD 64
#define CCH 128
#define KSMX 256
#define HSLOT (NBH*CCH*TSEQ)
#define WSLOT (CCH*CCH*KSMX)

static __device__ float g_Q[NBH*HD*TSEQ];
static __device__ float g_K[NBH*HD*TSEQ];
static __device__ float g_kagg[NBH*HD*TSEQ];
static __device__ float g_ksel[NBH*HD*TSEQ];
static __device__ float g_V[NBH*CCH*TSEQ];
static __device__ __align__(16) __half g_Vhs[4*HSLOT];      // 4 shifted copies of V (half)
static __device__ __align__(16) __half g_h1hs[4*6*HSLOT];   // 4 shifted copies of h1 (half)
static __device__ float g_h2[6*HSLOT];
static __device__ float g_agg[NBH*CCH*TSEQ];
static __device__ float g_X[2048*1024];
static __device__ __align__(16) __half g_w1h[6*WSLOT];
static __device__ __align__(16) __half g_w2h[6*WSLOT];
static __device__ float g_b1[6*CCH];
static __device__ float g_b2[6*CCH];
static __device__ float g_lcpart[8*NBH*TSEQ];
static __device__ float g_mc[TSEQ];
static __device__ float g_dimp[NBH*HD*HD];
static __device__ float g_tkw[HD*32];
static __device__ int   g_tkidx[HD*32];
static __device__ int   g_idx6[6];
static __device__ float g_tmp6[6];
static __device__ int   g_ks6[6];
static __device__ int   g_order[6];
static __device__ int   g_ctr[2];
static __device__ unsigned g_keys[6][4][2];

__device__ __forceinline__ unsigned rotl32(unsigned x, int r){ return (x<<r)|(x>>(32-r)); }

__device__ __forceinline__ void tf2x32(unsigned k0, unsigned k1, unsigned x0, unsigned x1,
                                       unsigned &o0, unsigned &o1){
  unsigned ks2 = 0x1BD11BDAu ^ k0 ^ k1;
  x0 += k0; x1 += k1;
#define TFR(r) { x0 += x1; x1 = rotl32(x1, r); x1 ^= x0; }
  TFR(13) TFR(15) TFR(26) TFR(6)
  x0 += k1;  x1 += ks2 + 1u;
  TFR(17) TFR(29) TFR(16) TFR(24)
  x0 += ks2; x1 += k0 + 2u;
  TFR(13) TFR(15) TFR(26) TFR(6)
  x0 += k0;  x1 += k1 + 3u;
  TFR(17) TFR(29) TFR(16) TFR(24)
  x0 += k1;  x1 += ks2 + 4u;
  TFR(13) TFR(15) TFR(26) TFR(6)
  x0 += ks2; x1 += k0 + 5u;
#undef TFR
  o0 = x0; o1 = x1;
}

__device__ __forceinline__ unsigned tf_bits(unsigned k0, unsigned k1, unsigned c){
  unsigned o0, o1; tf2x32(k0, k1, 0u, c, o0, o1);
  return o0 ^ o1;
}

__device__ __forceinline__ float bits_to_f01(unsigned bits){
  return __uint_as_float(0x3F800000u | (bits >> 9)) - 1.0f;
}

__device__ __forceinline__ float erfinv_xla(float x){
  float w = -log1pf(-x*x);
  float p;
  if (w < 5.0f) {
    w = w - 2.5f;
    p = 2.81022636e-08f;
    p = fmaf(p, w, 3.43273939e-07f);
    p = fmaf(p, w, -3.5233877e-06f);
    p = fmaf(p, w, -4.39150654e-06f);
    p = fmaf(p, w, 0.00021858087f);
    p = fmaf(p, w, -0.00125372503f);
    p = fmaf(p, w, -0.00417768164f);
    p = fmaf(p, w, 0.246640727f);
    p = fmaf(p, w, 1.50140941f);
  } else {
    w = sqrtf(w) - 3.0f;
    p = -0.000200214257f;
    p = fmaf(p, w, 0.000100950558f);
    p = fmaf(p, w, 0.00134934322f);
    p = fmaf(p, w, -0.00367342844f);
    p = fmaf(p, w, 0.00573950773f);
    p = fmaf(p, w, -0.0076224613f);
    p = fmaf(p, w, 0.00943887047f);
    p = fmaf(p, w, 1.00167406f);
    p = fmaf(p, w, 2.83297682f);
  }
  return p * x;
}

__device__ __forceinline__ float jax_normal_from_bits(unsigned bits){
  const float lo = __uint_as_float(0xBF7FFFFFu);
  float f = bits_to_f01(bits);
  float u = fmaxf(lo, fmaf(f, 2.0f, lo));
  return 1.41421356237309515f * erfinv_xla(u);
}

__device__ __forceinline__ uint32_t smem_u32(const void* p){
  uint32_t a;
  asm("{ .reg .u64 t; cvta.to.shared.u64 t, %1; cvt.u32.u64 %0, t; }" : "=r"(a) : "l"(p));
  return a;
}

// C[2048,512] = A[2048,K] @ B[512,K]^T + bias. mode 0/1/2 scatter to Q/K/V, 3 -> dstOut
__global__ void gemm_kernel(const float* __restrict__ A, const float* __restrict__ B,
                            const float* __restrict__ bias, float* __restrict__ dstOut,
                            int K, int mode){
  __shared__ float at[16][68];
  __shared__ float bt[16][68];
  int m0 = blockIdx.y * 64, n0 = blockIdx.x * 64;
  int tid = threadIdx.x;
  int tm = tid >> 4, tn = tid & 15;
  float acc[4][4] = {};
  for (int k0 = 0; k0 < K; k0 += 16){
    for (int l = tid; l < 1024; l += 256){
      int mm = l >> 4, kk = l & 15;
      at[kk][mm] = A[(size_t)(m0+mm)*K + k0 + kk];
      bt[kk][mm] = B[(size_t)(n0+mm)*K + k0 + kk];
    }
    __syncthreads();
#pragma unroll
    for (int kk = 0; kk < 16; kk++){
      float av[4], bv[4];
#pragma unroll
      for (int a = 0; a < 4; a++) av[a] = at[kk][tm*4+a];
#pragma unroll
      for (int b = 0; b < 4; b++) bv[b] = bt[kk][tn*4+b];
#pragma unroll
      for (int a = 0; a < 4; a++)
#pragma unroll
        for (int b = 0; b < 4; b++) acc[a][b] = fmaf(av[a], bv[b], acc[a][b]);
    }
    __syncthreads();
  }
#pragma unroll
  for (int a = 0; a < 4; a++){
#pragma unroll
    for (int b = 0; b < 4; b++){
      int m = m0 + tm*4 + a, n = n0 + tn*4 + b;
      float v = acc[a][b] + bias[n];
      if (mode == 3){
        dstOut[(size_t)m*512 + n] = v;
      } else {
        int t = m >> 2, bb = m & 3;
        int bh = bb*8 + (n >> 6), d = n & 63;
        if (mode == 0)      g_Q[((size_t)(bh*64 + d))*512 + t] = v;
        else if (mode == 1) g_K[((size_t)(bh*64 + d))*512 + t] = v;
        else {
          size_t idx = ((size_t)(bh*128 + d))*512 + t;
          g_V[idx] = v;
          g_Vhs[idx] = __float2half_rn(v);
        }
      }
    }
  }
}

__global__ void fillv2_kernel(const float* __restrict__ w){
  int gid = blockIdx.x*256 + threadIdx.x;
  if (gid >= NBH*64*TSEQ) return;
  int t = gid & 511, j = (gid >> 9) & 63, bh = gid >> 15;
  float v = w[j*32 + bh];
  size_t idx = ((size_t)(bh*128 + 64 + j))*512 + t;
  g_V[idx] = v;
  g_Vhs[idx] = __float2half_rn(v);
}

// build shifted copies 1..3 of V (copy c holds V[col+c], 0 past the end)
__global__ void vshift_kernel(){
  int i = blockIdx.x*256 + threadIdx.x;
  if (i >= HSLOT) return;
  int col = i & 511;
#pragma unroll
  for (int c = 1; c < 4; c++){
    __half v = (col + c < 512) ? g_Vhs[i + c] : __half(0.f);
    g_Vhs[(size_t)c*HSLOT + i] = v;
  }
}

// build shifted copies 1..3 of h1 (per active slot)
__global__ void h1shift_kernel(){
  int s = blockIdx.y;
  if (g_ks6[s] <= 1) return;
  int i = blockIdx.x*256 + threadIdx.x;
  if (i >= HSLOT) return;
  int col = i & 511;
  size_t base = (size_t)s*HSLOT + i;
#pragma unroll
  for (int c = 1; c < 4; c++){
    __half v = (col + c < 512) ? g_h1hs[base + c] : __half(0.f);
    g_h1hs[(size_t)c*(6*HSLOT) + base] = v;
  }
}

__global__ void cos_kernel(const float* __restrict__ w, float* __restrict__ out){
  __shared__ float ws[64][33];
  __shared__ float nrm[64];
  int i = threadIdx.x;
  float s = 0.f;
  for (int k = 0; k < 32; k++){ float x = w[i*32+k]; ws[i][k] = x; s += x*x; }
  nrm[i] = sqrtf(s);
  __syncthreads();
  float row[64];
  for (int j = 0; j < 64; j++){
    float d = 0.f;
    for (int k = 0; k < 32; k++) d += ws[i][k]*ws[j][k];
    row[j] = d / (nrm[i]*nrm[j]);
  }
  float mx = -3.0e38f;
  for (int j = 0; j < 64; j++) mx = fmaxf(mx, row[j]);
  float se = 0.f, e[64];
  for (int j = 0; j < 64; j++){ e[j] = expf(row[j]-mx); se += e[j]; }
  for (int j = 0; j < 64; j++) out[1048576 + 4096 + i*64 + j] = e[j]/se;
  float tmp[64];
  for (int j = 0; j < 64; j++) tmp[j] = row[j];
  float vals[32]; int idxs[32];
  for (int m = 0; m < 32; m++){
    float best = -3.0e38f; int bi = 0;
    for (int j = 0; j < 64; j++) if (tmp[j] > best){ best = tmp[j]; bi = j; }
    vals[m] = best; idxs[m] = bi; tmp[bi] = -3.0e38f;
  }
  float vse = 0.f, ve[32];
  for (int m = 0; m < 32; m++){ ve[m] = expf(vals[m]-vals[0]); vse += ve[m]; }
  for (int m = 0; m < 32; m++){ g_tkw[i*32+m] = ve[m]/vse; g_tkidx[i*32+m] = idxs[m]; }
}

__global__ void kagg_kernel(){
  int blk = blockIdx.x;
  int bh = blk >> 6, i = blk & 63;
  __shared__ float tw[32]; __shared__ int tix[32];
  if (threadIdx.x < 32){ tw[threadIdx.x] = g_tkw[i*32+threadIdx.x]; tix[threadIdx.x] = g_tkidx[i*32+threadIdx.x]; }
  __syncthreads();
  for (int u = threadIdx.x; u < 512; u += 128){
    float a = 0.f;
#pragma unroll
    for (int m = 0; m < 32; m++) a += tw[m] * g_K[((size_t)(bh*64 + tix[m]))*512 + u];
    g_kagg[((size_t)blk)*512 + u] = a;
  }
}

__global__ void lcorr_kernel(){
  int bh = blockIdx.x, ic = blockIdx.y;
  __shared__ float qs[512];
  __shared__ float kas[512];
  int t = threadIdx.x;
  float a0 = 0.f, a1 = 0.f;
  for (int i8 = 0; i8 < 8; i8++){
    int i = ic*8 + i8;
    for (int l = threadIdx.x; l < 512; l += 256){
      qs[l]  = g_Q[((size_t)(bh*64+i))*512 + l];
      kas[l] = g_kagg[((size_t)(bh*64+i))*512 + l];
    }
    __syncthreads();
    for (int u = 0; u < 512; u++){
      float qv = qs[u];
      a0 = fmaf(qv, kas[(u - t) & 511], a0);
      a1 = fmaf(qv, kas[(u - t - 256) & 511], a1);
    }
    __syncthreads();
  }
  g_lcpart[((size_t)(ic*32 + bh))*512 + t]       = a0;
  g_lcpart[((size_t)(ic*32 + bh))*512 + t + 256] = a1;
}

__global__ void lreduce_kernel(){
  int t = threadIdx.x;
  float mc = 0.f;
  for (int bh = 0; bh < 32; bh++){
    float lc = 0.f;
    for (int ic = 0; ic < 8; ic++) lc += g_lcpart[((size_t)(ic*32+bh))*512 + t];
    mc += lc * (1.0f/64.0f);
  }
  g_mc[t] = mc * (1.0f/32.0f);
}

// 32-thread top-6 with shuffle argmax (first-occurrence tie-break)
__global__ void top6_kernel(){
  int lane = threadIdx.x;
  float wv[6]; int wi[6];
  for (int r = 0; r < 6; r++){
    float best = -3.0e38f; int bi = 0x7fffffff;
    for (int j = 0; j < 16; j++){
      int t = lane + j*32;
      bool used = false;
      for (int p = 0; p < r; p++) if (wi[p] == t) used = true;
      float v = g_mc[t];
      if (!used && (v > best || (v == best && t < bi))){ best = v; bi = t; }
    }
    for (int o = 16; o; o >>= 1){
      float ov = __shfl_down_sync(0xffffffffu, best, o);
      int   oi = __shfl_down_sync(0xffffffffu, bi, o);
      if (ov > best || (ov == best && oi < bi)){ best = ov; bi = oi; }
    }
    best = __shfl_sync(0xffffffffu, best, 0);
    bi   = __shfl_sync(0xffffffffu, bi, 0);
    wv[r] = best; wi[r] = bi;
  }
  if (lane == 0){
    float mx = wv[0];
    for (int r = 1; r < 6; r++) mx = fmaxf(mx, wv[r]);
    float se = 0.f, e[6];
    for (int r = 0; r < 6; r++){ e[r] = expf(wv[r]-mx); se += e[r]; }
    for (int r = 0; r < 6; r++){ g_tmp6[r] = e[r]/se; g_idx6[r] = wi[r]; }
    for (int r = 0; r < 6; r++){
      int ind = wi[r];
      if (ind >= 256) ind = 512 - ind;
      g_ks6[r] = ind;
      if (ind > 1){
        unsigned f0, f1;
        tf2x32(0u, 1u, 0u, (unsigned)ind, f0, f1);
        for (int i = 0; i < 4; i++){
          unsigned o0, o1;
          tf2x32(f0, f1, 0u, (unsigned)i, o0, o1);
          g_keys[r][i][0] = o0; g_keys[r][i][1] = o1;
        }
      }
    }
    int ord[6], ksv[6];
    for (int r = 0; r < 6; r++){ ord[r] = r; ksv[r] = g_ks6[r]; }
    for (int a = 0; a < 5; a++){
      int best2 = a;
      for (int b = a+1; b < 6; b++) if (ksv[b] > ksv[best2]) best2 = b;
      int tk = ksv[a]; ksv[a] = ksv[best2]; ksv[best2] = tk;
      int to = ord[a]; ord[a] = ord[best2]; ord[best2] = to;
    }
    for (int r = 0; r < 6; r++) g_order[r] = ord[r];
    g_ctr[0] = 0; g_ctr[1] = 0;
  }
}

__global__ void ksel_kernel(){
  int blk = blockIdx.x;
  const float* kr = g_K + (size_t)blk*512;
  int idx[6]; float tc[6];
  for (int s = 0; s < 6; s++){ idx[s] = g_idx6[s]; tc[s] = g_tmp6[s]; }
  for (int u = threadIdx.x; u < 512; u += 128){
    float a = 0.f;
#pragma unroll
    for (int s = 0; s < 6; s++) a += tc[s] * kr[(u - idx[s]) & 511];
    g_ksel[(size_t)blk*512 + u] = a;
  }
}

__global__ void dimpart_kernel(){
  int bh = blockIdx.x;
  __shared__ float qt[64][65];
  __shared__ float kt[64][65];
  int tid = threadIdx.x;
  int ti = tid >> 4, tj = tid & 15;
  float acc[4][4] = {};
  for (int u0 = 0; u0 < 512; u0 += 64){
    for (int l = tid; l < 4096; l += 256){
      int ii = l >> 6, uu = l & 63;
      qt[ii][uu] = g_Q[((size_t)(bh*64+ii))*512 + u0 + uu];
      kt[ii][uu] = g_ksel[((size_t)(bh*64+ii))*512 + u0 + uu];
    }
    __syncthreads();
#pragma unroll 8
    for (int uu = 0; uu < 64; uu++){
      float qv[4], kv[4];
#pragma unroll
      for (int a = 0; a < 4; a++) qv[a] = qt[ti*4+a][uu];
#pragma unroll
      for (int c = 0; c < 4; c++) kv[c] = kt[tj*4+c][uu];
#pragma unroll
      for (int a = 0; a < 4; a++)
#pragma unroll
        for (int c = 0; c < 4; c++) acc[a][c] = fmaf(qv[a], kv[c], acc[a][c]);
    }
    __syncthreads();
  }
#pragma unroll
  for (int a = 0; a < 4; a++)
#pragma unroll
    for (int c = 0; c < 4; c++)
      g_dimp[(size_t)bh*4096 + (ti*4+a)*64 + (tj*4+c)] = acc[a][c];
}

__global__ void dimfinal_kernel(float* __restrict__ out){
  int i = threadIdx.x;
  float pre[64];
  for (int j = 0; j < 64; j++){
    float sh = 0.f;
    for (int h = 0; h < 8; h++){
      float sb = 0.f;
      for (int b = 0; b < 4; b++) sb += g_dimp[(size_t)(b*8+h)*4096 + i*64 + j];
      sh += sb * 0.25f;
    }
    pre[j] = 0.125f * (sh * 0.125f);
  }
  float mx = -3.0e38f;
  for (int j = 0; j < 64; j++) mx = fmaxf(mx, pre[j]);
  float se = 0.f, e[64];
  for (int j = 0; j < 64; j++){ e[j] = expf(pre[j]-mx); se += e[j]; }
  for (int j = 0; j < 64; j++) out[1048576 + i*64 + j] = e[j]/se;
}

// persistent weight generation; stores W in K'-transposed layout:
// offset = co*K + tau*128 + ci  for PRNG counter c = co*K + ci*ks + tau
__global__ void genW_kernel(){
  int pre[7]; pre[0] = 0;
  for (int s = 0; s < 6; s++){
    int ks = g_ks6[s];
    pre[s+1] = pre[s] + ((ks > 1) ? 32768*ks : 0);
  }
  int TOTAL = pre[6];
  for (int g = blockIdx.x*blockDim.x + threadIdx.x; g < TOTAL; g += gridDim.x*blockDim.x){
    int s = 0;
    while (g >= pre[s+1]) s++;
    int r = g - pre[s];
    int ks = g_ks6[s];
    int total = 16384*ks;
    int K = 128*ks;
    int which = (r >= total) ? 1 : 0;
    unsigned c = (unsigned)(which ? r - total : r);
    unsigned k0 = g_keys[s][which ? 2 : 0][0];
    unsigned k1 = g_keys[s][which ? 2 : 0][1];
    __half val = __float2half_rn(0.01f * jax_normal_from_bits(tf_bits(k0, k1, c)));
    int co = (int)c / K;
    int rem = (int)c - co*K;
    int ci = rem / ks;
    int tau = rem - ci*ks;
    size_t o = (size_t)s*WSLOT + (size_t)co*K + tau*128 + ci;
    if (which) g_w2h[o] = val;
    else       g_w1h[o] = val;
  }
}

__global__ void genB_kernel(){
  int s = blockIdx.x;
  int ks = g_ks6[s];
  if (ks <= 1) return;
  int tid = threadIdx.x;
  int which = tid >= 128;
  unsigned c = (unsigned)(tid & 127);
  unsigned k0 = g_keys[s][which ? 3 : 1][0];
  unsigned k1 = g_keys[s][which ? 3 : 1][1];
  float f = bits_to_f01(tf_bits(k0, k1, c));
  float bf = (float)(1.0 / sqrt((double)(128*ks)));
  float u = fmaxf(-bf, fmaf(f, 2.0f*bf, -bf));
  if (which) g_b2[s*CCH + c] = u; else g_b1[s*CCH + c] = u;
}

// ---- persistent fp16 mma implicit-GEMM conv; B in [k][t] layout via cp.async ----
#define ASTRH 40
#define ATILE (128*ASTRH)
#define BSTR 136
#define BTILE (32*BSTR)
#define NITEMS 768

__global__ void __launch_bounds__(128, 2) conv_tc_kernel(int which){
  __shared__ __half sA[2][ATILE];
  __shared__ __half sB[2][BTILE];
  __shared__ int s_item;

  const int tid = threadIdx.x;
  const int lane = tid & 31;
  const int warp = tid >> 5;
  const int gid = lane >> 2, tig = lane & 3;
  const int wm = warp & 1, wn = warp >> 1;

  const int kw = tid >> 2;          // B loader: row (ci offset)
  const int tseg = (tid & 3) * 32;  // B loader: 32-t segment

  for (;;){
    if (tid == 0) s_item = atomicAdd(&g_ctr[which], 1);
    __syncthreads();
    const int item = s_item;
    __syncthreads();
    if (item >= NITEMS) return;

    const int s = g_order[item >> 7];
    const int ks = g_ks6[s];
    if (ks <= 1) continue;
    const int rem = item & 127;
    const int bh = rem >> 2;
    const int t0 = (rem & 3) * 128;

    const __half* X0 = which ? (g_h1hs + (size_t)s*HSLOT) : g_Vhs;
    const size_t CST = which ? (size_t)(6*HSLOT) : (size_t)HSLOT;
    const __half* Xb = X0 + (size_t)bh*128*512;   // copy 0 base for this bh
    const __half* W = (which ? g_w2h : g_w1h) + (size_t)s*WSLOT;
    const float* Bv = (which ? g_b2 : g_b1) + s*CCH;
    const int K = 128*ks;
    const int nch = K >> 5;
    const int shift0 = t0 - (ks-1);

    float c[4][8][4];
#pragma unroll
    for (int mt = 0; mt < 4; mt++)
#pragma unroll
      for (int nt = 0; nt < 8; nt++)
#pragma unroll
        for (int r = 0; r < 4; r++) c[mt][nt][r] = 0.f;

    // ---- prologue: fill buffer 0 (chunk 0: tau=0, cig=0) ----
    {
      const __half* srcA = W + (size_t)tid*K;
      uint32_t dstA = smem_u32(&sA[0][tid*ASTRH]);
#pragma unroll
      for (int s4 = 0; s4 < 4; s4++)
        asm volatile("cp.async.cg.shared.global [%0], [%1], 16;"
                     :: "r"(dstA + 16*s4), "l"(srcA + 8*s4));
      const int ci = kw;
      const int off = shift0;
      const int lo = off + tseg;
      uint32_t dstB = smem_u32(&sB[0][kw*BSTR + tseg]);
      if (lo >= 0 && lo <= 480){
        int sel = off & 3;
        const __half* srcB = Xb + (size_t)sel*CST + (size_t)ci*512 + (lo - sel);
#pragma unroll
        for (int u = 0; u < 8; u++)
          asm volatile("cp.async.ca.shared.global [%0], [%1], 8;"
                       :: "r"(dstB + 8*u), "l"(srcB + 4*u));
      } else {
        __half* bp = &sB[0][kw*BSTR + tseg];
#pragma unroll
        for (int j = 0; j < 32; j++){
          int gc = lo + j;
          bp[j] = ((unsigned)gc < 512u) ? Xb[(size_t)ci*512 + gc] : __half(0.f);
        }
      }
      asm volatile("cp.async.commit_group;");
      asm volatile("cp.async.wait_group 0;");
    }
    __syncthreads();

    for (int ch = 0; ch < nch; ch++){
      const int p = ch & 1;
      const bool more = (ch+1 < nch);

      if (more){
        const int chn = ch+1;
        const __half* srcA = W + (size_t)tid*K + (chn << 5);
        uint32_t dstA = smem_u32(&sA[p^1][tid*ASTRH]);
#pragma unroll
        for (int s4 = 0; s4 < 4; s4++)
          asm volatile("cp.async.cg.shared.global [%0], [%1], 16;"
                       :: "r"(dstA + 16*s4), "l"(srcA + 8*s4));
        const int tau = chn >> 2;
        const int ci = ((chn & 3) << 5) + kw;
        const int off = shift0 + tau;
        const int lo = off + tseg;
        uint32_t dstB = smem_u32(&sB[p^1][kw*BSTR + tseg]);
        if (lo >= 0 && lo <= 480){
          int sel = off & 3;
          const __half* srcB = Xb + (size_t)sel*CST + (size_t)ci*512 + (lo - sel);
#pragma unroll
          for (int u = 0; u < 8; u++)
            asm volatile("cp.async.ca.shared.global [%0], [%1], 8;"
                         :: "r"(dstB + 8*u), "l"(srcB + 4*u));
        } else {
          __half* bp = &sB[p^1][kw*BSTR + tseg];
#pragma unroll
          for (int j = 0; j < 32; j++){
            int gc = lo + j;
            bp[j] = ((unsigned)gc < 512u) ? Xb[(size_t)ci*512 + gc] : __half(0.f);
          }
        }
        asm volatile("cp.async.commit_group;");
      }

      // fragment loads (A non-trans, B trans from [k][t]) + mma
      {
        uint32_t abase = smem_u32(&sA[p][0]);
        uint32_t bbase = smem_u32(&sB[p][0]);
        const int arow = wm*64 + (lane & 15);
        const int krow = ((lane >> 3) & 1)*8 + (lane & 7);
        const int tcol = wn*64 + ((lane >> 4) << 3);
#pragma unroll
        for (int kst = 0; kst < 2; kst++){
          unsigned a[4][4], b[4][4];
          uint32_t aoff = abase + (uint32_t)(arow*ASTRH + kst*16 + ((lane >> 4) << 3)) * 2u;
#pragma unroll
          for (int mt = 0; mt < 4; mt++){
            uint32_t ad = aoff + (uint32_t)(mt*16*ASTRH*2);
            asm volatile("ldmatrix.sync.aligned.m8n8.x4.shared.b16 {%0,%1,%2,%3}, [%4];"
              : "=r"(a[mt][0]), "=r"(a[mt][1]), "=r"(a[mt][2]), "=r"(a[mt][3]) : "r"(ad));
          }
          uint32_t boff = bbase + (uint32_t)((kst*16 + krow)*BSTR + tcol) * 2u;
#pragma unroll
          for (int ntp = 0; ntp < 4; ntp++){
            uint32_t bd = boff + (uint32_t)(ntp*16*2);
            asm volatile("ldmatrix.sync.aligned.m8n8.x4.trans.shared.b16 {%0,%1,%2,%3}, [%4];"
              : "=r"(b[ntp][0]), "=r"(b[ntp][1]), "=r"(b[ntp][2]), "=r"(b[ntp][3]) : "r"(bd));
          }
#pragma unroll
          for (int mt = 0; mt < 4; mt++)
#pragma unroll
            for (int nt = 0; nt < 8; nt++){
              unsigned b0 = b[nt >> 1][(nt & 1)*2 + 0];
              unsigned b1 = b[nt >> 1][(nt & 1)*2 + 1];
              asm volatile(
                "mma.sync.aligned.m16n8k16.row.col.f32.f16.f16.f32 "
                "{%0,%1,%2,%3}, {%4,%5,%6,%7}, {%8,%9}, {%0,%1,%2,%3};"
                : "+f"(c[mt][nt][0]), "+f"(c[mt][nt][1]),
                  "+f"(c[mt][nt][2]), "+f"(c[mt][nt][3])
                : "r"(a[mt][0]), "r"(a[mt][1]), "r"(a[mt][2]), "r"(a[mt][3]),
                  "r"(b0), "r"(b1));
            }
        }
      }

      if (more) asm volatile("cp.async.wait_group 0;");
      __syncthreads();
    }

    // epilogue: bias + relu; conv1 -> half copy0, conv2 -> f32
#pragma unroll
    for (int mt = 0; mt < 4; mt++){
      int co = wm*64 + mt*16 + gid;
      float bias0 = Bv[co], bias1 = Bv[co+8];
#pragma unroll
      for (int nt = 0; nt < 8; nt++){
        int t = t0 + wn*64 + nt*8 + 2*tig;
        float v0 = fmaxf(c[mt][nt][0] + bias0, 0.f);
        float v1 = fmaxf(c[mt][nt][1] + bias0, 0.f);
        float v2 = fmaxf(c[mt][nt][2] + bias1, 0.f);
        float v3 = fmaxf(c[mt][nt][3] + bias1, 0.f);
        if (which == 0){
          __half2* y0 = (__half2*)(g_h1hs + (size_t)s*HSLOT + ((size_t)(bh*128 + co))*512 + t);
          __half2* y1 = (__half2*)(g_h1hs + (size_t)s*HSLOT + ((size_t)(bh*128 + co + 8))*512 + t);
          *y0 = __halves2half2(__float2half_rn(v0), __float2half_rn(v1));
          *y1 = __halves2half2(__float2half_rn(v2), __float2half_rn(v3));
        } else {
          float* y0 = g_h2 + (size_t)s*HSLOT + ((size_t)(bh*128 + co))*512 + t;
          float* y1 = y0 + 8*512;
          y0[0] = v0; y0[1] = v1; y1[0] = v2; y1[1] = v3;
        }
      }
    }
    __syncthreads();
  }
}

__global__ void accum_all_kernel(){
  int gid = blockIdx.x*256 + threadIdx.x;
  if (gid >= NBH*CCH*TSEQ) return;
  float v = g_V[gid];
  float acc = 0.f;
#pragma unroll
  for (int s = 0; s < 6; s++){
    int ks = g_ks6[s];
    float tc = g_tmp6[s];
    float y = (ks <= 1) ? v : fmaxf(g_h2[(size_t)s*HSLOT + gid] + v, 0.f);
    acc += tc * y;
  }
  g_agg[gid] = acc;
}

__global__ void xpose_kernel(){
  int gid = blockIdx.x*256 + threadIdx.x;
  if (gid >= 2048*1024) return;
  int k = gid & 1023, m = gid >> 10;
  int b = m & 3, t = m >> 2;
  int h = k >> 7, c = k & 127;
  g_X[gid] = g_agg[((size_t)((b*8+h)*128 + c))*512 + t];
}

extern "C" void kernel_launch(void* const* d_in, const int* in_sizes, int n_in,
                              void* d_out, int out_size){
  const float* query = (const float*)d_in[0];
  const float* key_in = (const float*)d_in[1];
  const float* value = (const float*)d_in[2];
  const float* Wq = (const float*)d_in[4];
  const float* bq = (const float*)d_in[5];
  const float* Wk = (const float*)d_in[6];
  const float* bk = (const float*)d_in[7];
  const float* Wv = (const float*)d_in[8];
  const float* bv = (const float*)d_in[9];
  const float* Wo = (const float*)d_in[10];
  const float* bo = (const float*)d_in[11];
  const float* wa = (const float*)d_in[12];
  float* out = (float*)d_out;

  float* gX;   cudaGetSymbolAddress((void**)&gX, g_X);

  dim3 gproj(8, 32);
  gemm_kernel<<<gproj, 256>>>(query, Wq, bq, nullptr, 512, 0);
  gemm_kernel<<<gproj, 256>>>(key_in, Wk, bk, nullptr, 512, 1);
  gemm_kernel<<<gproj, 256>>>(value, Wv, bv, nullptr, 512, 2);
  fillv2_kernel<<<(NBH*64*TSEQ+255)/256, 256>>>(wa);
  vshift_kernel<<<(HSLOT+255)/256, 256>>>();
  cos_kernel<<<1, 64>>>(wa, out);
  kagg_kernel<<<2048, 128>>>();
  lcorr_kernel<<<dim3(32, 8), 256>>>();
  lreduce_kernel<<<1, 512>>>();
  top6_kernel<<<1, 32>>>();
  ksel_kernel<<<2048, 128>>>();
  dimpart_kernel<<<32, 256>>>();
  dimfinal_kernel<<<1, 64>>>(out);

  genW_kernel<<<1184, 256>>>();
  genB_kernel<<<6, 256>>>();
  conv_tc_kernel<<<296, 128>>>(0);
  h1shift_kernel<<<dim3((HSLOT+255)/256, 6), 256>>>();
  conv_tc_kernel<<<296, 128>>>(1);
  accum_all_kernel<<<(NBH*CCH*TSEQ+255)/256, 256>>>();
  xpose_kernel<<<(2048*1024+255)/256, 256>>>();
  gemm_kernel<<<gproj, 256>>>(gX, Wo, bo, out, 1024, 3);
}

// round 15
// speedup vs baseline: 1.4088x; 1.4088x over previous
#include <cuda_runtime.h>
#include <cuda_fp16.h>
#include <stdint.h>
#include <math.h>

#define TSEQ 512
#define NBH 32
#define HD 64
#define CCH 128
#define KSMX 256
#define HSLOT (NBH*CCH*TSEQ)
#define WSLOT (CCH*CCH*KSMX)

static __device__ float g_Q[NBH*HD*TSEQ];
static __device__ float g_K[NBH*HD*TSEQ];
static __device__ float g_kagg[NBH*HD*TSEQ];
static __device__ float g_ksel[NBH*HD*TSEQ];
static __device__ float g_V[NBH*CCH*TSEQ];
static __device__ __align__(16) __half g_Vh[NBH*CCH*TSEQ];
static __device__ __align__(16) __half g_h1h[6*HSLOT];
static __device__ float g_h2[6*HSLOT];
static __device__ float g_agg[NBH*CCH*TSEQ];
static __device__ float g_X[2048*1024];
static __device__ __align__(16) __half g_w1h[6*WSLOT];
static __device__ __align__(16) __half g_w2h[6*WSLOT];
static __device__ float g_b1[6*CCH];
static __device__ float g_b2[6*CCH];
static __device__ float g_lcpart[8*NBH*TSEQ];
static __device__ float g_mc[TSEQ];
static __device__ float g_dimp[NBH*HD*HD];
static __device__ float g_tkw[HD*32];
static __device__ int   g_tkidx[HD*32];
static __device__ int   g_idx6[6];
static __device__ float g_tmp6[6];
static __device__ int   g_ks6[6];
static __device__ int   g_order[6];
static __device__ int   g_ctr[2];
static __device__ unsigned g_keys[6][4][2];

__device__ __forceinline__ unsigned rotl32(unsigned x, int r){ return (x<<r)|(x>>(32-r)); }

__device__ __forceinline__ uint32_t h2u(__half h0, __half h1){
  __half2 h = __halves2half2(h0, h1);
  return *reinterpret_cast<uint32_t*>(&h);
}

__device__ __forceinline__ void tf2x32(unsigned k0, unsigned k1, unsigned x0, unsigned x1,
                                       unsigned &o0, unsigned &o1){
  unsigned ks2 = 0x1BD11BDAu ^ k0 ^ k1;
  x0 += k0; x1 += k1;
#define TFR(r) { x0 += x1; x1 = rotl32(x1, r); x1 ^= x0; }
  TFR(13) TFR(15) TFR(26) TFR(6)
  x0 += k1;  x1 += ks2 + 1u;
  TFR(17) TFR(29) TFR(16) TFR(24)
  x0 += ks2; x1 += k0 + 2u;
  TFR(13) TFR(15) TFR(26) TFR(6)
  x0 += k0;  x1 += k1 + 3u;
  TFR(17) TFR(29) TFR(16) TFR(24)
  x0 += k1;  x1 += ks2 + 4u;
  TFR(13) TFR(15) TFR(26) TFR(6)
  x0 += ks2; x1 += k0 + 5u;
#undef TFR
  o0 = x0; o1 = x1;
}

__device__ __forceinline__ unsigned tf_bits(unsigned k0, unsigned k1, unsigned c){
  unsigned o0, o1; tf2x32(k0, k1, 0u, c, o0, o1);
  return o0 ^ o1;
}

__device__ __forceinline__ float bits_to_f01(unsigned bits){
  return __uint_as_float(0x3F800000u | (bits >> 9)) - 1.0f;
}

__device__ __forceinline__ float erfinv_xla(float x){
  float w = -log1pf(-x*x);
  float p;
  if (w < 5.0f) {
    w = w - 2.5f;
    p = 2.81022636e-08f;
    p = fmaf(p, w, 3.43273939e-07f);
    p = fmaf(p, w, -3.5233877e-06f);
    p = fmaf(p, w, -4.39150654e-06f);
    p = fmaf(p, w, 0.00021858087f);
    p = fmaf(p, w, -0.00125372503f);
    p = fmaf(p, w, -0.00417768164f);
    p = fmaf(p, w, 0.246640727f);
    p = fmaf(p, w, 1.50140941f);
  } else {
    w = sqrtf(w) - 3.0f;
    p = -0.000200214257f;
    p = fmaf(p, w, 0.000100950558f);
    p = fmaf(p, w, 0.00134934322f);
    p = fmaf(p, w, -0.00367342844f);
    p = fmaf(p, w, 0.00573950773f);
    p = fmaf(p, w, -0.0076224613f);
    p = fmaf(p, w, 0.00943887047f);
    p = fmaf(p, w, 1.00167406f);
    p = fmaf(p, w, 2.83297682f);
  }
  return p * x;
}

__device__ __forceinline__ float jax_normal_from_bits(unsigned bits){
  const float lo = __uint_as_float(0xBF7FFFFFu);
  float f = bits_to_f01(bits);
  float u = fmaxf(lo, fmaf(f, 2.0f, lo));
  return 1.41421356237309515f * erfinv_xla(u);
}

__device__ __forceinline__ uint32_t smem_u32(const void* p){
  uint32_t a;
  asm("{ .reg .u64 t; cvta.to.shared.u64 t, %1; cvt.u32.u64 %0, t; }" : "=r"(a) : "l"(p));
  return a;
}

// C[2048,512] = A[2048,K] @ B[512,K]^T + bias. mode 0/1/2 scatter to Q/K/V, 3 -> dstOut
__global__ void gemm_kernel(const float* __restrict__ A, const float* __restrict__ B,
                            const float* __restrict__ bias, float* __restrict__ dstOut,
                            int K, int mode){
  __shared__ float at[16][68];
  __shared__ float bt[16][68];
  int m0 = blockIdx.y * 64, n0 = blockIdx.x * 64;
  int tid = threadIdx.x;
  int tm = tid >> 4, tn = tid & 15;
  float acc[4][4] = {};
  for (int k0 = 0; k0 < K; k0 += 16){
    for (int l = tid; l < 1024; l += 256){
      int mm = l >> 4, kk = l & 15;
      at[kk][mm] = A[(size_t)(m0+mm)*K + k0 + kk];
      bt[kk][mm] = B[(size_t)(n0+mm)*K + k0 + kk];
    }
    __syncthreads();
#pragma unroll
    for (int kk = 0; kk < 16; kk++){
      float av[4], bv[4];
#pragma unroll
      for (int a = 0; a < 4; a++) av[a] = at[kk][tm*4+a];
#pragma unroll
      for (int b = 0; b < 4; b++) bv[b] = bt[kk][tn*4+b];
#pragma unroll
      for (int a = 0; a < 4; a++)
#pragma unroll
        for (int b = 0; b < 4; b++) acc[a][b] = fmaf(av[a], bv[b], acc[a][b]);
    }
    __syncthreads();
  }
#pragma unroll
  for (int a = 0; a < 4; a++){
#pragma unroll
    for (int b = 0; b < 4; b++){
      int m = m0 + tm*4 + a, n = n0 + tn*4 + b;
      float v = acc[a][b] + bias[n];
      if (mode == 3){
        dstOut[(size_t)m*512 + n] = v;
      } else {
        int t = m >> 2, bb = m & 3;
        int bh = bb*8 + (n >> 6), d = n & 63;
        if (mode == 0)      g_Q[((size_t)(bh*64 + d))*512 + t] = v;
        else if (mode == 1) g_K[((size_t)(bh*64 + d))*512 + t] = v;
        else {
          size_t idx = ((size_t)(bh*128 + d))*512 + t;
          g_V[idx] = v;
          g_Vh[idx] = __float2half_rn(v);
        }
      }
    }
  }
}

__global__ void fillv2_kernel(const float* __restrict__ w){
  int gid = blockIdx.x*256 + threadIdx.x;
  if (gid >= NBH*64*TSEQ) return;
  int t = gid & 511, j = (gid >> 9) & 63, bh = gid >> 15;
  float v = w[j*32 + bh];
  size_t idx = ((size_t)(bh*128 + 64 + j))*512 + t;
  g_V[idx] = v;
  g_Vh[idx] = __float2half_rn(v);
}

__global__ void cos_kernel(const float* __restrict__ w, float* __restrict__ out){
  __shared__ float ws[64][33];
  __shared__ float nrm[64];
  int i = threadIdx.x;
  float s = 0.f;
  for (int k = 0; k < 32; k++){ float x = w[i*32+k]; ws[i][k] = x; s += x*x; }
  nrm[i] = sqrtf(s);
  __syncthreads();
  float row[64];
  for (int j = 0; j < 64; j++){
    float d = 0.f;
    for (int k = 0; k < 32; k++) d += ws[i][k]*ws[j][k];
    row[j] = d / (nrm[i]*nrm[j]);
  }
  float mx = -3.0e38f;
  for (int j = 0; j < 64; j++) mx = fmaxf(mx, row[j]);
  float se = 0.f, e[64];
  for (int j = 0; j < 64; j++){ e[j] = expf(row[j]-mx); se += e[j]; }
  for (int j = 0; j < 64; j++) out[1048576 + 4096 + i*64 + j] = e[j]/se;
  float tmp[64];
  for (int j = 0; j < 64; j++) tmp[j] = row[j];
  float vals[32]; int idxs[32];
  for (int m = 0; m < 32; m++){
    float best = -3.0e38f; int bi = 0;
    for (int j = 0; j < 64; j++) if (tmp[j] > best){ best = tmp[j]; bi = j; }
    vals[m] = best; idxs[m] = bi; tmp[bi] = -3.0e38f;
  }
  float vse = 0.f, ve[32];
  for (int m = 0; m < 32; m++){ ve[m] = expf(vals[m]-vals[0]); vse += ve[m]; }
  for (int m = 0; m < 32; m++){ g_tkw[i*32+m] = ve[m]/vse; g_tkidx[i*32+m] = idxs[m]; }
}

__global__ void kagg_kernel(){
  int blk = blockIdx.x;
  int bh = blk >> 6, i = blk & 63;
  __shared__ float tw[32]; __shared__ int tix[32];
  if (threadIdx.x < 32){ tw[threadIdx.x] = g_tkw[i*32+threadIdx.x]; tix[threadIdx.x] = g_tkidx[i*32+threadIdx.x]; }
  __syncthreads();
  for (int u = threadIdx.x; u < 512; u += 128){
    float a = 0.f;
#pragma unroll
    for (int m = 0; m < 32; m++) a += tw[m] * g_K[((size_t)(bh*64 + tix[m]))*512 + u];
    g_kagg[((size_t)blk)*512 + u] = a;
  }
}

__global__ void lcorr_kernel(){
  int bh = blockIdx.x, ic = blockIdx.y;
  __shared__ float qs[512];
  __shared__ float kas[512];
  int t = threadIdx.x;
  float a0 = 0.f, a1 = 0.f;
  for (int i8 = 0; i8 < 8; i8++){
    int i = ic*8 + i8;
    for (int l = threadIdx.x; l < 512; l += 256){
      qs[l]  = g_Q[((size_t)(bh*64+i))*512 + l];
      kas[l] = g_kagg[((size_t)(bh*64+i))*512 + l];
    }
    __syncthreads();
    for (int u = 0; u < 512; u++){
      float qv = qs[u];
      a0 = fmaf(qv, kas[(u - t) & 511], a0);
      a1 = fmaf(qv, kas[(u - t - 256) & 511], a1);
    }
    __syncthreads();
  }
  g_lcpart[((size_t)(ic*32 + bh))*512 + t]       = a0;
  g_lcpart[((size_t)(ic*32 + bh))*512 + t + 256] = a1;
}

__global__ void lreduce_kernel(){
  int t = threadIdx.x;
  float mc = 0.f;
  for (int bh = 0; bh < 32; bh++){
    float lc = 0.f;
    for (int ic = 0; ic < 8; ic++) lc += g_lcpart[((size_t)(ic*32+bh))*512 + t];
    mc += lc * (1.0f/64.0f);
  }
  g_mc[t] = mc * (1.0f/32.0f);
}

// 32-thread top-6 with shuffle argmax (first-occurrence tie-break)
__global__ void top6_kernel(){
  int lane = threadIdx.x;
  float wv[6]; int wi[6];
  for (int r = 0; r < 6; r++){
    float best = -3.0e38f; int bi = 0x7fffffff;
    for (int j = 0; j < 16; j++){
      int t = lane + j*32;
      bool used = false;
      for (int p = 0; p < r; p++) if (wi[p] == t) used = true;
      float v = g_mc[t];
      if (!used && (v > best || (v == best && t < bi))){ best = v; bi = t; }
    }
    for (int o = 16; o; o >>= 1){
      float ov = __shfl_down_sync(0xffffffffu, best, o);
      int   oi = __shfl_down_sync(0xffffffffu, bi, o);
      if (ov > best || (ov == best && oi < bi)){ best = ov; bi = oi; }
    }
    best = __shfl_sync(0xffffffffu, best, 0);
    bi   = __shfl_sync(0xffffffffu, bi, 0);
    wv[r] = best; wi[r] = bi;
  }
  if (lane == 0){
    float mx = wv[0];
    for (int r = 1; r < 6; r++) mx = fmaxf(mx, wv[r]);
    float se = 0.f, e[6];
    for (int r = 0; r < 6; r++){ e[r] = expf(wv[r]-mx); se += e[r]; }
    for (int r = 0; r < 6; r++){ g_tmp6[r] = e[r]/se; g_idx6[r] = wi[r]; }
    for (int r = 0; r < 6; r++){
      int ind = wi[r];
      if (ind >= 256) ind = 512 - ind;
      g_ks6[r] = ind;
      if (ind > 1){
        unsigned f0, f1;
        tf2x32(0u, 1u, 0u, (unsigned)ind, f0, f1);
        for (int i = 0; i < 4; i++){
          unsigned o0, o1;
          tf2x32(f0, f1, 0u, (unsigned)i, o0, o1);
          g_keys[r][i][0] = o0; g_keys[r][i][1] = o1;
        }
      }
    }
    int ord[6], ksv[6];
    for (int r = 0; r < 6; r++){ ord[r] = r; ksv[r] = g_ks6[r]; }
    for (int a = 0; a < 5; a++){
      int best2 = a;
      for (int b = a+1; b < 6; b++) if (ksv[b] > ksv[best2]) best2 = b;
      int tk = ksv[a]; ksv[a] = ksv[best2]; ksv[best2] = tk;
      int to = ord[a]; ord[a] = ord[best2]; ord[best2] = to;
    }
    for (int r = 0; r < 6; r++) g_order[r] = ord[r];
    g_ctr[0] = 0; g_ctr[1] = 0;
  }
}

__global__ void ksel_kernel(){
  int blk = blockIdx.x;
  const float* kr = g_K + (size_t)blk*512;
  int idx[6]; float tc[6];
  for (int s = 0; s < 6; s++){ idx[s] = g_idx6[s]; tc[s] = g_tmp6[s]; }
  for (int u = threadIdx.x; u < 512; u += 128){
    float a = 0.f;
#pragma unroll
    for (int s = 0; s < 6; s++) a += tc[s] * kr[(u - idx[s]) & 511];
    g_ksel[(size_t)blk*512 + u] = a;
  }
}

__global__ void dimpart_kernel(){
  int bh = blockIdx.x;
  __shared__ float qt[64][65];
  __shared__ float kt[64][65];
  int tid = threadIdx.x;
  int ti = tid >> 4, tj = tid & 15;
  float acc[4][4] = {};
  for (int u0 = 0; u0 < 512; u0 += 64){
    for (int l = tid; l < 4096; l += 256){
      int ii = l >> 6, uu = l & 63;
      qt[ii][uu] = g_Q[((size_t)(bh*64+ii))*512 + u0 + uu];
      kt[ii][uu] = g_ksel[((size_t)(bh*64+ii))*512 + u0 + uu];
    }
    __syncthreads();
#pragma unroll 8
    for (int uu = 0; uu < 64; uu++){
      float qv[4], kv[4];
#pragma unroll
      for (int a = 0; a < 4; a++) qv[a] = qt[ti*4+a][uu];
#pragma unroll
      for (int c = 0; c < 4; c++) kv[c] = kt[tj*4+c][uu];
#pragma unroll
      for (int a = 0; a < 4; a++)
#pragma unroll
        for (int c = 0; c < 4; c++) acc[a][c] = fmaf(qv[a], kv[c], acc[a][c]);
    }
    __syncthreads();
  }
#pragma unroll
  for (int a = 0; a < 4; a++)
#pragma unroll
    for (int c = 0; c < 4; c++)
      g_dimp[(size_t)bh*4096 + (ti*4+a)*64 + (tj*4+c)] = acc[a][c];
}

__global__ void dimfinal_kernel(float* __restrict__ out){
  int i = threadIdx.x;
  float pre[64];
  for (int j = 0; j < 64; j++){
    float sh = 0.f;
    for (int h = 0; h < 8; h++){
      float sb = 0.f;
      for (int b = 0; b < 4; b++) sb += g_dimp[(size_t)(b*8+h)*4096 + i*64 + j];
      sh += sb * 0.25f;
    }
    pre[j] = 0.125f * (sh * 0.125f);
  }
  float mx = -3.0e38f;
  for (int j = 0; j < 64; j++) mx = fmaxf(mx, pre[j]);
  float se = 0.f, e[64];
  for (int j = 0; j < 64; j++){ e[j] = expf(pre[j]-mx); se += e[j]; }
  for (int j = 0; j < 64; j++) out[1048576 + i*64 + j] = e[j]/se;
}

// persistent weight generation; stores W in K'-transposed layout:
// offset = co*K + tau*128 + ci  for PRNG counter c = co*K + ci*ks + tau
__global__ void genW_kernel(){
  int pre[7]; pre[0] = 0;
  for (int s = 0; s < 6; s++){
    int ks = g_ks6[s];
    pre[s+1] = pre[s] + ((ks > 1) ? 32768*ks : 0);
  }
  int TOTAL = pre[6];
  for (int g = blockIdx.x*blockDim.x + threadIdx.x; g < TOTAL; g += gridDim.x*blockDim.x){
    int s = 0;
    while (g >= pre[s+1]) s++;
    int r = g - pre[s];
    int ks = g_ks6[s];
    int total = 16384*ks;
    int K = 128*ks;
    int which = (r >= total) ? 1 : 0;
    unsigned c = (unsigned)(which ? r - total : r);
    unsigned k0 = g_keys[s][which ? 2 : 0][0];
    unsigned k1 = g_keys[s][which ? 2 : 0][1];
    __half val = __float2half_rn(0.01f * jax_normal_from_bits(tf_bits(k0, k1, c)));
    int co = (int)c / K;
    int rem = (int)c - co*K;
    int ci = rem / ks;
    int tau = rem - ci*ks;
    size_t o = (size_t)s*WSLOT + (size_t)co*K + tau*128 + ci;
    if (which) g_w2h[o] = val;
    else       g_w1h[o] = val;
  }
}

__global__ void genB_kernel(){
  int s = blockIdx.x;
  int ks = g_ks6[s];
  if (ks <= 1) return;
  int tid = threadIdx.x;
  int which = tid >= 128;
  unsigned c = (unsigned)(tid & 127);
  unsigned k0 = g_keys[s][which ? 3 : 1][0];
  unsigned k1 = g_keys[s][which ? 3 : 1][1];
  float f = bits_to_f01(tf_bits(k0, k1, c));
  float bf = (float)(1.0 / sqrt((double)(128*ks)));
  float u = fmaxf(-bf, fmaf(f, 2.0f*bf, -bf));
  if (which) g_b2[s*CCH + c] = u; else g_b1[s*CCH + c] = u;
}

// ---- persistent fp16 mma implicit-GEMM conv; K' = tau*128+ci; 256 threads / 8 warps ----
#define ASTRH 40
#define TILEH (128*ASTRH)
#define NITEMS 768

__global__ void __launch_bounds__(256, 2) conv_tc_kernel(int which){
  __shared__ __half sA[2][TILEH];
  __shared__ __half sB[2][TILEH];
  __shared__ int s_item;

  const int tid = threadIdx.x;
  const int lane = tid & 31;
  const int warp = tid >> 5;
  const int gid = lane >> 2, tig = lane & 3;
  const int wm = warp & 3;      // 4 m-tiles of 32 co
  const int wn = warp >> 2;     // 2 n-tiles of 64 t

  const int tv = tid >> 1;              // loader row (0..127)
  const int khalf = (tid & 1) * 16;     // loader k-half

  for (;;){
    if (tid == 0) s_item = atomicAdd(&g_ctr[which], 1);
    __syncthreads();
    const int item = s_item;
    __syncthreads();
    if (item >= NITEMS) return;

    const int s = g_order[item >> 7];
    const int ks = g_ks6[s];
    if (ks <= 1) continue;
    const int rem = item & 127;
    const int bh = rem >> 2;
    const int t0 = (rem & 3) * 128;

    const __half* X = which ? (g_h1h + (size_t)s*HSLOT) : g_Vh;
    const __half* W = (which ? g_w2h : g_w1h) + (size_t)s*WSLOT;
    const float* Bv = (which ? g_b2 : g_b1) + s*CCH;
    const __half* Xb = X + (size_t)bh*128*512;
    const int K = 128*ks;
    const int nch = K >> 5;

    const int gbase = t0 + tv - (ks-1);   // B row tv's shift at tau=0

    float c[2][8][4];
#pragma unroll
    for (int mt = 0; mt < 2; mt++)
#pragma unroll
      for (int nt = 0; nt < 8; nt++)
#pragma unroll
        for (int r = 0; r < 4; r++) c[mt][nt][r] = 0.f;

    // ---- prologue: chunk 0 (tau=0, ci = khalf..khalf+16) ----
    {
      const __half* srcA = W + (size_t)tv*K + khalf;
      uint32_t dstA = smem_u32(&sA[0][tv*ASTRH + khalf]);
      asm volatile("cp.async.cg.shared.global [%0], [%1], 16;" :: "r"(dstA), "l"(srcA));
      asm volatile("cp.async.cg.shared.global [%0], [%1], 16;" :: "r"(dstA+16), "l"(srcA+8));
      asm volatile("cp.async.commit_group;");
      uint32_t* bw = (uint32_t*)&sB[0][tv*ASTRH + khalf];
      int g = gbase;
      if ((unsigned)g < 512u){
        const __half* xp = Xb + (size_t)khalf*512 + g;
#pragma unroll
        for (int j = 0; j < 8; j++){
          __half h0 = xp[0];
          __half h1 = xp[512];
          xp += 1024;
          bw[j] = h2u(h0, h1);
        }
      } else {
#pragma unroll
        for (int j = 0; j < 8; j++) bw[j] = 0u;
      }
      asm volatile("cp.async.wait_group 0;");
    }
    __syncthreads();

    uint32_t br[8];

    for (int ch = 0; ch < nch; ch++){
      const int p = ch & 1;
      const bool more = (ch+1 < nch);

      if (more){
        const int chn = ch+1;
        const __half* srcA = W + (size_t)tv*K + (chn << 5) + khalf;
        uint32_t dstA = smem_u32(&sA[p^1][tv*ASTRH + khalf]);
        asm volatile("cp.async.cg.shared.global [%0], [%1], 16;" :: "r"(dstA), "l"(srcA));
        asm volatile("cp.async.cg.shared.global [%0], [%1], 16;" :: "r"(dstA+16), "l"(srcA+8));
        asm volatile("cp.async.commit_group;");
        const int tau = chn >> 2;
        const int ci0 = ((chn & 3) << 5) + khalf;
        int g = gbase + tau;
        if ((unsigned)g < 512u){
          const __half* xp = Xb + (size_t)ci0*512 + g;
#pragma unroll
          for (int j = 0; j < 8; j++){
            __half h0 = xp[0];
            __half h1 = xp[512];
            xp += 1024;
            br[j] = h2u(h0, h1);
          }
        } else {
#pragma unroll
          for (int j = 0; j < 8; j++) br[j] = 0u;
        }
      }

      // fragment loads via ldmatrix + mma
      {
        uint32_t abase = smem_u32(&sA[p][0]);
        uint32_t bbase = smem_u32(&sB[p][0]);
        const int arow = wm*32 + (lane & 15);
        const int brow = wn*64 + (lane & 7) + ((lane >> 4) << 3);
#pragma unroll
        for (int kst = 0; kst < 2; kst++){
          unsigned a[2][4], b[4][4];
          uint32_t aoff = abase + (uint32_t)(arow*ASTRH + kst*16 + ((lane >> 4) << 3)) * 2u;
          uint32_t boff = bbase + (uint32_t)(brow*ASTRH + kst*16 + (((lane >> 3) & 1) << 3)) * 2u;
#pragma unroll
          for (int mt = 0; mt < 2; mt++){
            uint32_t ad = aoff + (uint32_t)(mt*16*ASTRH*2);
            asm volatile("ldmatrix.sync.aligned.m8n8.x4.shared.b16 {%0,%1,%2,%3}, [%4];"
              : "=r"(a[mt][0]), "=r"(a[mt][1]), "=r"(a[mt][2]), "=r"(a[mt][3]) : "r"(ad));
          }
#pragma unroll
          for (int ntp = 0; ntp < 4; ntp++){
            uint32_t bd = boff + (uint32_t)(ntp*16*ASTRH*2);
            asm volatile("ldmatrix.sync.aligned.m8n8.x4.shared.b16 {%0,%1,%2,%3}, [%4];"
              : "=r"(b[ntp][0]), "=r"(b[ntp][1]), "=r"(b[ntp][2]), "=r"(b[ntp][3]) : "r"(bd));
          }
#pragma unroll
          for (int mt = 0; mt < 2; mt++)
#pragma unroll
            for (int nt = 0; nt < 8; nt++){
              unsigned b0 = b[nt >> 1][(nt & 1)*2 + 0];
              unsigned b1 = b[nt >> 1][(nt & 1)*2 + 1];
              asm volatile(
                "mma.sync.aligned.m16n8k16.row.col.f32.f16.f16.f32 "
                "{%0,%1,%2,%3}, {%4,%5,%6,%7}, {%8,%9}, {%0,%1,%2,%3};"
                : "+f"(c[mt][nt][0]), "+f"(c[mt][nt][1]),
                  "+f"(c[mt][nt][2]), "+f"(c[mt][nt][3])
                : "r"(a[mt][0]), "r"(a[mt][1]), "r"(a[mt][2]), "r"(a[mt][3]),
                  "r"(b0), "r"(b1));
            }
        }
      }

      if (more){
        uint32_t* bwn = (uint32_t*)&sB[p^1][tv*ASTRH + khalf];
#pragma unroll
        for (int j = 0; j < 8; j++) bwn[j] = br[j];
        asm volatile("cp.async.wait_group 0;");
      }
      __syncthreads();
    }

    // epilogue: bias + relu; conv1 -> half, conv2 -> f32
#pragma unroll
    for (int mt = 0; mt < 2; mt++){
      int co = wm*32 + mt*16 + gid;
      float bias0 = Bv[co], bias1 = Bv[co+8];
#pragma unroll
      for (int nt = 0; nt < 8; nt++){
        int t = t0 + wn*64 + nt*8 + 2*tig;
        float v0 = fmaxf(c[mt][nt][0] + bias0, 0.f);
        float v1 = fmaxf(c[mt][nt][1] + bias0, 0.f);
        float v2 = fmaxf(c[mt][nt][2] + bias1, 0.f);
        float v3 = fmaxf(c[mt][nt][3] + bias1, 0.f);
        if (which == 0){
          __half2* y0 = (__half2*)(g_h1h + (size_t)s*HSLOT + ((size_t)(bh*128 + co))*512 + t);
          __half2* y1 = (__half2*)(g_h1h + (size_t)s*HSLOT + ((size_t)(bh*128 + co + 8))*512 + t);
          *y0 = __halves2half2(__float2half_rn(v0), __float2half_rn(v1));
          *y1 = __halves2half2(__float2half_rn(v2), __float2half_rn(v3));
        } else {
          float* y0 = g_h2 + (size_t)s*HSLOT + ((size_t)(bh*128 + co))*512 + t;
          float* y1 = y0 + 8*512;
          y0[0] = v0; y0[1] = v1; y1[0] = v2; y1[1] = v3;
        }
      }
    }
    __syncthreads();
  }
}

__global__ void accum_all_kernel(){
  int gid = blockIdx.x*256 + threadIdx.x;
  if (gid >= NBH*CCH*TSEQ) return;
  float v = g_V[gid];
  float acc = 0.f;
#pragma unroll
  for (int s = 0; s < 6; s++){
    int ks = g_ks6[s];
    float tc = g_tmp6[s];
    float y = (ks <= 1) ? v : fmaxf(g_h2[(size_t)s*HSLOT + gid] + v, 0.f);
    acc += tc * y;
  }
  g_agg[gid] = acc;
}

__global__ void xpose_kernel(){
  int gid = blockIdx.x*256 + threadIdx.x;
  if (gid >= 2048*1024) return;
  int k = gid & 1023, m = gid >> 10;
  int b = m & 3, t = m >> 2;
  int h = k >> 7, c = k & 127;
  g_X[gid] = g_agg[((size_t)((b*8+h)*128 + c))*512 + t];
}

extern "C" void kernel_launch(void* const* d_in, const int* in_sizes, int n_in,
                              void* d_out, int out_size){
  const float* query = (const float*)d_in[0];
  const float* key_in = (const float*)d_in[1];
  const float* value = (const float*)d_in[2];
  const float* Wq = (const float*)d_in[4];
  const float* bq = (const float*)d_in[5];
  const float* Wk = (const float*)d_in[6];
  const float* bk = (const float*)d_in[7];
  const float* Wv = (const float*)d_in[8];
  const float* bv = (const float*)d_in[9];
  const float* Wo = (const float*)d_in[10];
  const float* bo = (const float*)d_in[11];
  const float* wa = (const float*)d_in[12];
  float* out = (float*)d_out;

  float* gX;   cudaGetSymbolAddress((void**)&gX, g_X);

  dim3 gproj(8, 32);
  gemm_kernel<<<gproj, 256>>>(query, Wq, bq, nullptr, 512, 0);
  gemm_kernel<<<gproj, 256>>>(key_in, Wk, bk, nullptr, 512, 1);
  gemm_kernel<<<gproj, 256>>>(value, Wv, bv, nullptr, 512, 2);
  fillv2_kernel<<<(NBH*64*TSEQ+255)/256, 256>>>(wa);
  cos_kernel<<<1, 64>>>(wa, out);
  kagg_kernel<<<2048, 128>>>();
  lcorr_kernel<<<dim3(32, 8), 256>>>();
  lreduce_kernel<<<1, 512>>>();
  top6_kernel<<<1, 32>>>();
  ksel_kernel<<<2048, 128>>>();
  dimpart_kernel<<<32, 256>>>();
  dimfinal_kernel<<<1, 64>>>(out);

  genW_kernel<<<1184, 256>>>();
  genB_kernel<<<6, 256>>>();
  conv_tc_kernel<<<296, 256>>>(0);
  conv_tc_kernel<<<296, 256>>>(1);
  accum_all_kernel<<<(NBH*CCH*TSEQ+255)/256, 256>>>();
  xpose_kernel<<<(2048*1024+255)/256, 256>>>();
  gemm_kernel<<<gproj, 256>>>(gX, Wo, bo, out, 1024, 3);
}